// round 13
// baseline (speedup 1.0000x reference)
#include <cuda_runtime.h>
#include <cuda_bf16.h>
#include <stdint.h>
#include <stddef.h>

// ---------------- Problem constants ----------------
static constexpr int B_ = 8;
static constexpr int N_ = 4096;
static constexpr int D_ = 512;
static constexpr int TILE = 128;
static constexpr int NTILE = N_ / TILE;              // 32
static constexpr int NTRI = NTILE * (NTILE + 1) / 2; // 528 upper-tri tiles per batch
static constexpr int KCHUNK = 64;                    // bf16 elems per K chunk (128 B/row)
static constexpr int NKC = D_ / KCHUNK;              // 8 chunks
static constexpr int NSTG = 3;                       // cp.async pipeline stages

// ---------------- SMEM layout (bytes) ----------------
static constexpr int SM_SQI   = 0;                   // 128 floats
static constexpr int SM_RDI   = 512;
static constexpr int SM_SQJ   = 1024;
static constexpr int SM_RDJ   = 1536;
static constexpr int SM_TILES = 2048;                // 3 stages x (A 16K + B 16K)
static constexpr int STG_SZ   = 32768;
static constexpr int SM_TOTAL = SM_TILES + NSTG * STG_SZ;  // 100352 B -> 2 CTAs/SM
static constexpr int SM_STAGE = SM_TILES;            // epilogue staging (tiles dead by then)
static constexpr int STAGE_STRIDE = 36;              // floats; 16B-aligned rows, conflict-free

// ---------------- Scratch (device globals; allocation-free) ----------------
__device__ __nv_bfloat16 g_xb[(size_t)B_ * N_ * D_]; // 32 MiB bf16 projected x
__device__ float g_sq[B_ * N_];                      // ||x_i||^2 (fp32)
__device__ float g_rd[B_ * N_];                      // sqrt(2)/(1-||x_i||^2)

// ---------------- PTX helpers (family-portable: sm_80+/75+) ----------------
__device__ __forceinline__ uint32_t smem_u32(const void* p) {
    uint32_t a;
    asm("{ .reg .u64 t; cvta.to.shared.u64 t, %1; cvt.u32.u64 %0, t; }" : "=r"(a) : "l"(p));
    return a;
}
__device__ __forceinline__ void cp16(uint32_t dst, const void* src) {
    asm volatile("cp.async.cg.shared.global [%0], [%1], 16;" :: "r"(dst), "l"(src) : "memory");
}
__device__ __forceinline__ void cp_commit() {
    asm volatile("cp.async.commit_group;" ::: "memory");
}
__device__ __forceinline__ void ldsm4(uint32_t* r, uint32_t addr) {
    asm volatile("ldmatrix.sync.aligned.m8n8.x4.shared.b16 {%0,%1,%2,%3}, [%4];"
                 : "=r"(r[0]), "=r"(r[1]), "=r"(r[2]), "=r"(r[3]) : "r"(addr));
}
__device__ __forceinline__ void mma16816(float* c, const uint32_t* a, uint32_t b0, uint32_t b1) {
    asm volatile(
        "mma.sync.aligned.m16n8k16.row.col.f32.bf16.bf16.f32 "
        "{%0,%1,%2,%3}, {%4,%5,%6,%7}, {%8,%9}, {%0,%1,%2,%3};"
        : "+f"(c[0]), "+f"(c[1]), "+f"(c[2]), "+f"(c[3])
        : "r"(a[0]), "r"(a[1]), "r"(a[2]), "r"(a[3]), "r"(b0), "r"(b1));
}
__device__ __forceinline__ float fsqrt_ap(float x) {
    float r; asm("sqrt.approx.f32 %0, %1;" : "=f"(r) : "f"(x)); return r;
}
__device__ __forceinline__ float flg2_ap(float x) {
    float r; asm("lg2.approx.f32 %0, %1;" : "=f"(r) : "f"(x)); return r;
}
__device__ __forceinline__ uint32_t swz(uint32_t off) {   // SW128-style XOR swizzle
    return off ^ ((off >> 3) & 0x70);
}

// ---------------- Prep: proj (dead for this input), sq, sqrt2/(1-sq), bf16 cast ----------------
__global__ void __launch_bounds__(128) prep_kernel(const float* __restrict__ emb) {
    const int row = blockIdx.x;                 // b*N + n
    const int t = threadIdx.x;                  // 4 floats per thread
    const int w = t >> 5, l = t & 31;
    __shared__ float ws[4];

    float4 v = reinterpret_cast<const float4*>(emb + (size_t)row * D_)[t];
    float p = v.x * v.x + v.y * v.y + v.z * v.z + v.w * v.w;
    #pragma unroll
    for (int o = 16; o; o >>= 1) p += __shfl_xor_sync(0xffffffffu, p, o);
    if (l == 0) ws[w] = p;
    __syncthreads();
    float sq = ws[0] + ws[1] + ws[2] + ws[3];   // uniform across block

    if (sqrtf(sq) >= 1.0f) {                    // faithful to ref __proj; dead here
        const float inv = 1.0f / sqrtf(sq);
        const float EPS = 1e-5f;
        v.x = v.x * inv - EPS; v.y = v.y * inv - EPS;
        v.z = v.z * inv - EPS; v.w = v.w * inv - EPS;
        float p2 = v.x * v.x + v.y * v.y + v.z * v.z + v.w * v.w;
        #pragma unroll
        for (int o = 16; o; o >>= 1) p2 += __shfl_xor_sync(0xffffffffu, p2, o);
        __syncthreads();
        if (l == 0) ws[w] = p2;
        __syncthreads();
        sq = ws[0] + ws[1] + ws[2] + ws[3];
    }

    __nv_bfloat162* dst = reinterpret_cast<__nv_bfloat162*>(g_xb + (size_t)row * D_) + t * 2;
    dst[0] = __floats2bfloat162_rn(v.x, v.y);
    dst[1] = __floats2bfloat162_rn(v.z, v.w);
    if (t == 0) {
        g_sq[row] = sq;
        g_rd[row] = 1.4142135623730951f / (1.0f - sq);  // sqrt2 factor: rd_i*rd_j carries the 2x
    }
}

// ---------------- One K-chunk (128 rows x 64 bf16) for A and B, swizzled ----------------
__device__ __forceinline__ void load_chunk(const __nv_bfloat16* __restrict__ Xb,
                                           int arow0, int brow0, int kc,
                                           uint32_t stage_base, int tid) {
    const int row = tid >> 1, half = tid & 1;
    const char* ag = (const char*)(Xb + (size_t)(arow0 + row) * D_ + kc * KCHUNK) + half * 64;
    const char* bg = (const char*)(Xb + (size_t)(brow0 + row) * D_ + kc * KCHUNK) + half * 64;
    const uint32_t abase = stage_base, bbase = stage_base + 16384;
    #pragma unroll
    for (int u = 0; u < 4; u++) {
        uint32_t off = (uint32_t)(row * 128 + half * 64 + u * 16);
        uint32_t sw = swz(off);
        cp16(abase + sw, ag + u * 16);
        cp16(bbase + sw, bg + u * 16);
    }
    cp_commit();   // one group per thread per chunk
}

// ---------------- MMA over one resident K-chunk: B first, A rotated under mma ----------------
__device__ __forceinline__ void mma_chunk(uint32_t stage_base, int m0, int n0,
                                          int lr, int lcg, float acc[4][4][4]) {
    const uint32_t ab = stage_base;
    const uint32_t bb = stage_base + 16384;
    #pragma unroll
    for (int kk = 0; kk < 4; kk++) {
        const uint32_t bc = (uint32_t)(kk * 32 + lcg * 16);     // < 128
        uint32_t bfr[2][4];
        #pragma unroll
        for (int np = 0; np < 2; np++) {
            const uint32_t row = (uint32_t)((n0 + np * 16 + lr) * 128);
            ldsm4(bfr[np], bb + row + (bc ^ ((row >> 3) & 0x70)));
        }
        uint32_t afr[2][4];
        {   // preload A frag for mf=0
            const uint32_t row = (uint32_t)((m0 + lr) * 128);
            ldsm4(afr[0], ab + row + (bc ^ ((row >> 3) & 0x70)));
        }
        #pragma unroll
        for (int mf = 0; mf < 4; mf++) {
            if (mf < 3) {   // rotate in next A frag while current mma runs
                const uint32_t row = (uint32_t)((m0 + (mf + 1) * 16 + lr) * 128);
                ldsm4(afr[(mf + 1) & 1], ab + row + (bc ^ ((row >> 3) & 0x70)));
            }
            #pragma unroll
            for (int nf = 0; nf < 4; nf++) {
                const int np = nf >> 1, sub = nf & 1;
                mma16816(acc[mf][nf], afr[mf & 1], bfr[np][sub], bfr[np][sub + 2]);
            }
        }
    }
}

// ---------------- Fused Gram + hyperbolic distance, one 128x128 upper-tri tile ----------------
// 256 threads = 8 warps in a 2(m) x 4(n) grid; warp tile 64x32.
__global__ void __launch_bounds__(256, 2) hyp_gemm_kernel(float* __restrict__ out) {
    extern __shared__ char smem[];
    const uint32_t sb = smem_u32(smem);
    const int tid = threadIdx.x;
    const int wid = tid >> 5;
    const int lid = tid & 31;
    const int m0 = (wid >> 2) * 64;   // warp m offset in tile
    const int n0 = (wid & 3) * 32;    // warp n offset in tile
    const int b = blockIdx.y;

    // decode upper-triangular tile (ti <= tj)
    int ti = 0, rem = blockIdx.x;
    while (rem >= NTILE - ti) { rem -= NTILE - ti; ti++; }
    const int tj = ti + rem;
    const bool diag = (ti == tj);

    const __nv_bfloat16* Xb = g_xb + (size_t)b * N_ * D_;
    const int arow0 = ti * TILE, brow0 = tj * TILE;
    const uint32_t stg0 = sb + SM_TILES;
    const uint32_t stg1 = stg0 + STG_SZ;
    const uint32_t stg2 = stg1 + STG_SZ;

    // kick off first two K-chunks immediately
    load_chunk(Xb, arow0, brow0, 0, stg0, tid);
    load_chunk(Xb, arow0, brow0, 1, stg1, tid);

    // row/col norm terms into smem
    if (tid < 128) {
        ((float*)(smem + SM_SQI))[tid] = g_sq[b * N_ + arow0 + tid];
        ((float*)(smem + SM_RDI))[tid] = g_rd[b * N_ + arow0 + tid];
    } else {
        const int t2 = tid - 128;
        ((float*)(smem + SM_SQJ))[t2] = g_sq[b * N_ + brow0 + t2];
        ((float*)(smem + SM_RDJ))[t2] = g_rd[b * N_ + brow0 + t2];
    }

    float acc[4][4][4];
    #pragma unroll
    for (int mf = 0; mf < 4; mf++)
        #pragma unroll
        for (int nf = 0; nf < 4; nf++)
            #pragma unroll
            for (int e = 0; e < 4; e++) acc[mf][nf][e] = 0.0f;

    const int lr = lid & 15;   // ldmatrix row within 16
    const int lcg = lid >> 4;  // ldmatrix 16B col group

    // 3-stage pipeline, one __syncthreads per chunk, next load issued before mma
    #pragma unroll
    for (int c = 0; c < NKC; c++) {
        if (c < NKC - 1) asm volatile("cp.async.wait_group 1;" ::: "memory");
        else             asm volatile("cp.async.wait_group 0;" ::: "memory");
        __syncthreads();                      // chunk c visible; stage (c+2)%3 drained

        const uint32_t cur = (c % 3 == 0) ? stg0 : (c % 3 == 1) ? stg1 : stg2;
        if (c + 2 < NKC) {
            const int s = (c + 2) % 3;
            load_chunk(Xb, arow0, brow0, c + 2, s == 0 ? stg0 : s == 1 ? stg1 : stg2, tid);
        }
        mma_chunk(cur, m0, n0, lr, lcg, acc);
    }
    __syncthreads();                          // tiles dead; staging region reuse safe

    // ---------------- Epilogue ----------------
    // C frag mapping (m16n8): lane = g*4+t; e0:(g,2t) e1:(g,2t+1) e2:(g+8,2t) e3:(g+8,2t+1)
    const int g = lid >> 2, t = lid & 3;
    const float* sqi = (const float*)(smem + SM_SQI);
    const float* rdi = (const float*)(smem + SM_RDI);
    const float* sqj = (const float*)(smem + SM_SQJ);
    const float* rdj = (const float*)(smem + SM_RDJ);
    float* outb = out + (size_t)b * N_ * N_;
    float* stage = (float*)(smem + SM_STAGE) + wid * (32 * STAGE_STRIDE);
    const float LN2 = 0.6931471805599453f;

    #pragma unroll
    for (int pass = 0; pass < 2; pass++) {    // m-halves of the warp tile
        // transform accumulators in place: G -> dist
        #pragma unroll
        for (int mfl = 0; mfl < 2; mfl++) {
            const int mf = pass * 2 + mfl;
            #pragma unroll
            for (int e2 = 0; e2 < 2; e2++) {            // e>>1: row-half select
                const int r_loc = m0 + pass * 32 + mfl * 16 + g + 8 * e2;
                const float sq_r = sqi[r_loc];
                const float rd_r = rdi[r_loc];
                #pragma unroll
                for (int nf = 0; nf < 4; nf++) {
                    #pragma unroll
                    for (int e1 = 0; e1 < 2; e1++) {    // e&1: col select
                        const int c_loc = n0 + nf * 8 + 2 * t + e1;
                        const int e = e2 * 2 + e1;
                        const float G = acc[mf][nf][e];
                        const float d2 = fmaxf(sq_r + sqj[c_loc] - 2.0f * G, 0.0f);
                        const float s = fsqrt_ap(d2);
                        const float w = fmaf(rd_r * rdj[c_loc], s, 1.0f);  // rd carries sqrt2 each
                        const float q = fsqrt_ap(fmaf(w, w, -1.0f));
                        float dv = (w > 1.0f) ? flg2_ap(w + q) * LN2 : 0.0f;
                        if (diag && r_loc == c_loc) dv = 0.0f;   // exact diagonal zero
                        acc[mf][nf][e] = dv;
                    }
                }
            }
        }
        // straight writes out[I][J]: float2 stcs; one row base per (mfl,rh)
        #pragma unroll
        for (int mfl = 0; mfl < 2; mfl++) {
            const int mf = pass * 2 + mfl;
            #pragma unroll
            for (int rh = 0; rh < 2; rh++) {
                const int I = arow0 + m0 + pass * 32 + mfl * 16 + g + 8 * rh;
                float* rowp = outb + (size_t)I * N_ + (brow0 + n0 + 2 * t);
                #pragma unroll
                for (int nf = 0; nf < 4; nf++) {
                    float2 v2 = make_float2(acc[mf][nf][rh * 2], acc[mf][nf][rh * 2 + 1]);
                    __stcs(reinterpret_cast<float2*>(rowp + nf * 8), v2);
                }
            }
        }
        // mirror writes out[J][I] via per-warp padded smem transpose (skip on diag tiles)
        if (!diag) {
            #pragma unroll
            for (int mfl = 0; mfl < 2; mfl++) {
                const int mf = pass * 2 + mfl;
                #pragma unroll
                for (int nf = 0; nf < 4; nf++) {
                    #pragma unroll
                    for (int e = 0; e < 4; e++) {
                        const int r_loc = mfl * 16 + g + 8 * (e >> 1);   // 0..31 within pass
                        const int c_loc = nf * 8 + 2 * t + (e & 1);      // 0..31 within warp
                        stage[c_loc * STAGE_STRIDE + r_loc] = acc[mf][nf][e];
                    }
                }
            }
            __syncwarp();
            // vectorized readback: lane handles row c = c0 + (lid>>3), 16B chunk cg = lid&7
            const int crow = lid >> 3, cg4 = (lid & 7) * 4;
            float* colbase = outb + (size_t)(brow0 + n0 + crow) * N_ +
                             (arow0 + m0 + pass * 32 + cg4);
            #pragma unroll
            for (int c0 = 0; c0 < 32; c0 += 4) {
                const float4 v4 = *reinterpret_cast<const float4*>(
                    stage + (c0 + crow) * STAGE_STRIDE + cg4);
                __stcs(reinterpret_cast<float4*>(colbase), v4);
                colbase += (size_t)4 * N_;
            }
            __syncwarp();                     // staging reuse next pass
        }
    }
}

// ---------------- Launch ----------------
extern "C" void kernel_launch(void* const* d_in, const int* in_sizes, int n_in,
                              void* d_out, int out_size) {
    (void)in_sizes; (void)n_in; (void)out_size;
    const float* emb = (const float*)d_in[0];
    float* out = (float*)d_out;

    cudaFuncSetAttribute(hyp_gemm_kernel,
                         cudaFuncAttributeMaxDynamicSharedMemorySize, SM_TOTAL);

    prep_kernel<<<B_ * N_, 128>>>(emb);
    dim3 grid(NTRI, B_);
    hyp_gemm_kernel<<<grid, 256, SM_TOTAL>>>(out);
}

// round 15
// speedup vs baseline: 1.4828x; 1.4828x over previous
#include <cuda_runtime.h>
#include <cuda_bf16.h>
#include <stdint.h>
#include <stddef.h>

// ---------------- Problem constants ----------------
static constexpr int B_ = 8;
static constexpr int N_ = 4096;
static constexpr int D_ = 512;
static constexpr int TILE = 128;
static constexpr int NTILE = N_ / TILE;              // 32
static constexpr int NTRI = NTILE * (NTILE + 1) / 2; // 528 upper-tri tiles per batch
static constexpr int KCHUNK = 64;                    // bf16 elems per K chunk (128 B/row)
static constexpr int NKC = D_ / KCHUNK;              // 8 chunks
static constexpr int NSTG = 3;                       // cp.async pipeline stages

// ---------------- SMEM layout (bytes) ----------------
static constexpr int SM_SQI   = 0;                   // 128 floats
static constexpr int SM_RDI   = 512;
static constexpr int SM_SQJ   = 1024;
static constexpr int SM_RDJ   = 1536;
static constexpr int SM_TILES = 2048;                // 3 stages x (A 16K + B 16K)
static constexpr int STG_SZ   = 32768;
static constexpr int SM_TOTAL = SM_TILES + NSTG * STG_SZ;  // 100352 B -> 2 CTAs/SM

// ---------------- Scratch (device globals; allocation-free) ----------------
__device__ __nv_bfloat16 g_xb[(size_t)B_ * N_ * D_]; // 32 MiB bf16 projected x
__device__ float g_sq[B_ * N_];                      // ||x_i||^2 (fp32)
__device__ float g_rd[B_ * N_];                      // sqrt(2)/(1-||x_i||^2)

// ---------------- PTX helpers (family-portable: sm_80+/75+) ----------------
__device__ __forceinline__ uint32_t smem_u32(const void* p) {
    uint32_t a;
    asm("{ .reg .u64 t; cvta.to.shared.u64 t, %1; cvt.u32.u64 %0, t; }" : "=r"(a) : "l"(p));
    return a;
}
__device__ __forceinline__ void cp16(uint32_t dst, const void* src) {
    asm volatile("cp.async.cg.shared.global [%0], [%1], 16;" :: "r"(dst), "l"(src) : "memory");
}
__device__ __forceinline__ void cp_commit() {
    asm volatile("cp.async.commit_group;" ::: "memory");
}
__device__ __forceinline__ void ldsm4(uint32_t* r, uint32_t addr) {
    asm volatile("ldmatrix.sync.aligned.m8n8.x4.shared.b16 {%0,%1,%2,%3}, [%4];"
                 : "=r"(r[0]), "=r"(r[1]), "=r"(r[2]), "=r"(r[3]) : "r"(addr));
}
__device__ __forceinline__ void mma16816(float* c, const uint32_t* a, uint32_t b0, uint32_t b1) {
    asm volatile(
        "mma.sync.aligned.m16n8k16.row.col.f32.bf16.bf16.f32 "
        "{%0,%1,%2,%3}, {%4,%5,%6,%7}, {%8,%9}, {%0,%1,%2,%3};"
        : "+f"(c[0]), "+f"(c[1]), "+f"(c[2]), "+f"(c[3])
        : "r"(a[0]), "r"(a[1]), "r"(a[2]), "r"(a[3]), "r"(b0), "r"(b1));
}
__device__ __forceinline__ float fsqrt_ap(float x) {
    float r; asm("sqrt.approx.f32 %0, %1;" : "=f"(r) : "f"(x)); return r;
}
__device__ __forceinline__ float flg2_ap(float x) {
    float r; asm("lg2.approx.f32 %0, %1;" : "=f"(r) : "f"(x)); return r;
}
__device__ __forceinline__ uint32_t swz(uint32_t off) {   // SW128-style XOR swizzle
    return off ^ ((off >> 3) & 0x70);
}

// ---------------- Prep: proj (dead for this input), sq, sqrt2/(1-sq), bf16 cast ----------------
__global__ void __launch_bounds__(128) prep_kernel(const float* __restrict__ emb) {
    const int row = blockIdx.x;                 // b*N + n
    const int t = threadIdx.x;                  // 4 floats per thread
    const int w = t >> 5, l = t & 31;
    __shared__ float ws[4];

    float4 v = reinterpret_cast<const float4*>(emb + (size_t)row * D_)[t];
    float p = v.x * v.x + v.y * v.y + v.z * v.z + v.w * v.w;
    #pragma unroll
    for (int o = 16; o; o >>= 1) p += __shfl_xor_sync(0xffffffffu, p, o);
    if (l == 0) ws[w] = p;
    __syncthreads();
    float sq = ws[0] + ws[1] + ws[2] + ws[3];   // uniform across block

    if (sqrtf(sq) >= 1.0f) {                    // faithful to ref __proj; dead here
        const float inv = 1.0f / sqrtf(sq);
        const float EPS = 1e-5f;
        v.x = v.x * inv - EPS; v.y = v.y * inv - EPS;
        v.z = v.z * inv - EPS; v.w = v.w * inv - EPS;
        float p2 = v.x * v.x + v.y * v.y + v.z * v.z + v.w * v.w;
        #pragma unroll
        for (int o = 16; o; o >>= 1) p2 += __shfl_xor_sync(0xffffffffu, p2, o);
        __syncthreads();
        if (l == 0) ws[w] = p2;
        __syncthreads();
        sq = ws[0] + ws[1] + ws[2] + ws[3];
    }

    __nv_bfloat162* dst = reinterpret_cast<__nv_bfloat162*>(g_xb + (size_t)row * D_) + t * 2;
    dst[0] = __floats2bfloat162_rn(v.x, v.y);
    dst[1] = __floats2bfloat162_rn(v.z, v.w);
    if (t == 0) {
        g_sq[row] = sq;
        g_rd[row] = 1.4142135623730951f / (1.0f - sq);  // sqrt2 each: rd_i*rd_j carries the 2x
    }
}

// ---------------- One K-chunk (128 rows x 64 bf16) for A and B, swizzled ----------------
__device__ __forceinline__ void load_chunk(const __nv_bfloat16* __restrict__ Xb,
                                           int arow0, int brow0, int kc,
                                           uint32_t stage_base, int tid) {
    const int row = tid >> 1, half = tid & 1;
    const char* ag = (const char*)(Xb + (size_t)(arow0 + row) * D_ + kc * KCHUNK) + half * 64;
    const char* bg = (const char*)(Xb + (size_t)(brow0 + row) * D_ + kc * KCHUNK) + half * 64;
    const uint32_t abase = stage_base, bbase = stage_base + 16384;
    #pragma unroll
    for (int u = 0; u < 4; u++) {
        uint32_t off = (uint32_t)(row * 128 + half * 64 + u * 16);
        uint32_t sw = swz(off);
        cp16(abase + sw, ag + u * 16);
        cp16(bbase + sw, bg + u * 16);
    }
    cp_commit();   // one group per thread per chunk
}

// ---------------- MMA over one resident K-chunk (batched ldsm, then 16 mma) ----------------
__device__ __forceinline__ void mma_chunk(uint32_t stage_base, int m0, int n0,
                                          int lr, int lcg, float acc[4][4][4]) {
    const uint32_t ab = stage_base;
    const uint32_t bb = stage_base + 16384;
    #pragma unroll
    for (int kk = 0; kk < 4; kk++) {
        const uint32_t bc = (uint32_t)(kk * 32 + lcg * 16);     // < 128
        // batch all fragment loads first: 6 ldmatrix.x4 in flight, then dense mma
        uint32_t bfr[2][4];
        #pragma unroll
        for (int np = 0; np < 2; np++) {
            const uint32_t row = (uint32_t)((n0 + np * 16 + lr) * 128);
            ldsm4(bfr[np], bb + row + (bc ^ ((row >> 3) & 0x70)));
        }
        uint32_t afr[4][4];
        #pragma unroll
        for (int mf = 0; mf < 4; mf++) {
            const uint32_t row = (uint32_t)((m0 + mf * 16 + lr) * 128);
            ldsm4(afr[mf], ab + row + (bc ^ ((row >> 3) & 0x70)));
        }
        #pragma unroll
        for (int mf = 0; mf < 4; mf++)
            #pragma unroll
            for (int nf = 0; nf < 4; nf++) {
                const int np = nf >> 1, sub = nf & 1;
                mma16816(acc[mf][nf], afr[mf], bfr[np][sub], bfr[np][sub + 2]);
            }
    }
}

// ---------------- Fused Gram + hyperbolic distance, one 128x128 upper-tri tile ----------------
// 256 threads = 8 warps in a 2(m) x 4(n) grid; warp tile 64x32.
__global__ void __launch_bounds__(256, 2) hyp_gemm_kernel(float* __restrict__ out) {
    extern __shared__ char smem[];
    const uint32_t sb = smem_u32(smem);
    const int tid = threadIdx.x;
    const int wid = tid >> 5;
    const int lid = tid & 31;
    const int m0 = (wid >> 2) * 64;   // warp m offset in tile
    const int n0 = (wid & 3) * 32;    // warp n offset in tile
    const int b = blockIdx.y;

    // decode upper-triangular tile (ti <= tj)
    int ti = 0, rem = blockIdx.x;
    while (rem >= NTILE - ti) { rem -= NTILE - ti; ti++; }
    const int tj = ti + rem;
    const bool diag = (ti == tj);

    const __nv_bfloat16* Xb = g_xb + (size_t)b * N_ * D_;
    const int arow0 = ti * TILE, brow0 = tj * TILE;
    const uint32_t stg0 = sb + SM_TILES;
    const uint32_t stg1 = stg0 + STG_SZ;
    const uint32_t stg2 = stg1 + STG_SZ;

    // kick off first two K-chunks immediately
    load_chunk(Xb, arow0, brow0, 0, stg0, tid);
    load_chunk(Xb, arow0, brow0, 1, stg1, tid);

    // row/col norm terms into smem
    if (tid < 128) {
        ((float*)(smem + SM_SQI))[tid] = g_sq[b * N_ + arow0 + tid];
        ((float*)(smem + SM_RDI))[tid] = g_rd[b * N_ + arow0 + tid];
    } else {
        const int t2 = tid - 128;
        ((float*)(smem + SM_SQJ))[t2] = g_sq[b * N_ + brow0 + t2];
        ((float*)(smem + SM_RDJ))[t2] = g_rd[b * N_ + brow0 + t2];
    }

    float acc[4][4][4];
    #pragma unroll
    for (int mf = 0; mf < 4; mf++)
        #pragma unroll
        for (int nf = 0; nf < 4; nf++)
            #pragma unroll
            for (int e = 0; e < 4; e++) acc[mf][nf][e] = 0.0f;

    const int lr = lid & 15;   // ldmatrix row within 16
    const int lcg = lid >> 4;  // ldmatrix 16B col group

    // 3-stage pipeline, one __syncthreads per chunk, next load issued before mma
    #pragma unroll
    for (int c = 0; c < NKC; c++) {
        if (c < NKC - 1) asm volatile("cp.async.wait_group 1;" ::: "memory");
        else             asm volatile("cp.async.wait_group 0;" ::: "memory");
        __syncthreads();                      // chunk c visible; stage (c+2)%3 drained

        const uint32_t cur = (c % 3 == 0) ? stg0 : (c % 3 == 1) ? stg1 : stg2;
        if (c + 2 < NKC) {
            const int s = (c + 2) % 3;
            load_chunk(Xb, arow0, brow0, c + 2, s == 0 ? stg0 : s == 1 ? stg1 : stg2, tid);
        }
        mma_chunk(cur, m0, n0, lr, lcg, acc);
    }
    // no trailing __syncthreads needed: epilogue reads only SQ/RD smem written pre-mainloop

    // ---------------- Epilogue ----------------
    // C frag mapping (m16n8): lane = g*4+t; e0:(g,2t) e1:(g,2t+1) e2:(g+8,2t) e3:(g+8,2t+1)
    const int g = lid >> 2, t = lid & 3;
    const float* sqi = (const float*)(smem + SM_SQI);
    const float* rdi = (const float*)(smem + SM_RDI);
    const float* sqj = (const float*)(smem + SM_SQJ);
    const float* rdj = (const float*)(smem + SM_RDJ);
    float* outb = out + (size_t)b * N_ * N_;
    const float LN2 = 0.6931471805599453f;

    // transform ALL accumulators in place: G -> dist
    #pragma unroll
    for (int mf = 0; mf < 4; mf++) {
        #pragma unroll
        for (int e2 = 0; e2 < 2; e2++) {                // e>>1: row-half select
            const int r_loc = m0 + mf * 16 + g + 8 * e2;
            const float sq_r = sqi[r_loc];
            const float rd_r = rdi[r_loc];
            #pragma unroll
            for (int nf = 0; nf < 4; nf++) {
                #pragma unroll
                for (int e1 = 0; e1 < 2; e1++) {        // e&1: col select
                    const int c_loc = n0 + nf * 8 + 2 * t + e1;
                    const int e = e2 * 2 + e1;
                    const float G = acc[mf][nf][e];
                    const float d2 = fmaxf(sq_r + sqj[c_loc] - 2.0f * G, 0.0f);
                    const float s = fsqrt_ap(d2);
                    const float w = fmaf(rd_r * rdj[c_loc], s, 1.0f);  // rd carries sqrt2 each
                    const float q = fsqrt_ap(fmaf(w, w, -1.0f));
                    float dv = (w > 1.0f) ? flg2_ap(w + q) * LN2 : 0.0f;
                    if (diag && r_loc == c_loc) dv = 0.0f;   // exact diagonal zero
                    acc[mf][nf][e] = dv;
                }
            }
        }
    }

    // straight writes out[I][J]: float2 stcs; hoisted row pointers, immediate offsets
    {
        float* rowp0 = outb + (size_t)(arow0 + m0 + g) * N_ + (brow0 + n0 + 2 * t);
        #pragma unroll
        for (int mf = 0; mf < 4; mf++) {
            #pragma unroll
            for (int rh = 0; rh < 2; rh++) {
                float* rowp = rowp0 + (size_t)(mf * 16 + rh * 8) * N_;
                #pragma unroll
                for (int nf = 0; nf < 4; nf++) {
                    float2 v2 = make_float2(acc[mf][nf][rh * 2], acc[mf][nf][rh * 2 + 1]);
                    __stcs(reinterpret_cast<float2*>(rowp + nf * 8), v2);
                }
            }
        }
    }

    // mirror writes out[J][I] directly from registers (skip on diag tiles).
    // Per unrolled (mf,nf,e): 8 g-lanes write 32 contiguous bytes of row c_loc ->
    // full 32B sectors; 4 stores fully cover each 128B line. 8 hoisted row
    // pointers; all offsets compile-time immediates.
    if (!diag) {
        float* mrow[8];   // indexed by nf*2+e1
        #pragma unroll
        for (int nf = 0; nf < 4; nf++)
            #pragma unroll
            for (int e1 = 0; e1 < 2; e1++)
                mrow[nf * 2 + e1] = outb +
                    (size_t)(brow0 + n0 + nf * 8 + 2 * t + e1) * N_ + (arow0 + m0 + g);
        #pragma unroll
        for (int mf = 0; mf < 4; mf++)
            #pragma unroll
            for (int nf = 0; nf < 4; nf++)
                #pragma unroll
                for (int e = 0; e < 4; e++)
                    __stcs(mrow[nf * 2 + (e & 1)] + mf * 16 + 8 * (e >> 1), acc[mf][nf][e]);
    }
}

// ---------------- Launch ----------------
extern "C" void kernel_launch(void* const* d_in, const int* in_sizes, int n_in,
                              void* d_out, int out_size) {
    (void)in_sizes; (void)n_in; (void)out_size;
    const float* emb = (const float*)d_in[0];
    float* out = (float*)d_out;

    cudaFuncSetAttribute(hyp_gemm_kernel,
                         cudaFuncAttributeMaxDynamicSharedMemorySize, SM_TOTAL);

    prep_kernel<<<B_ * N_, 128>>>(emb);
    dim3 grid(NTRI, B_);
    hyp_gemm_kernel<<<grid, 256, SM_TOTAL>>>(out);
}